// round 8
// baseline (speedup 1.0000x reference)
#include <cuda_runtime.h>

#define BB 16
#define SS 2048
#define FF 64
#define RR (BB*SS)
#define SC 256          // sub-chunks per batch (granularity 8)
#define SCM 8
#define NQ 4            // quarters per batch in k2

// ---- scratch (device globals; no allocations allowed) ----
__device__ __align__(128) float g_ts[SS];
__device__ __align__(128) int   g_perm[SS];
__device__ __align__(128) float g_us[SS];
__device__ __align__(128) float g_vs[SS];
__device__ __align__(128) float g_P[SS+1];
__device__ __align__(128) float g_Q[SS+1];
__device__ __align__(128) float g_PU8[BB*SC*FF];  // quarter-LOCAL exclusive prefix of u*f
__device__ __align__(128) float g_QV8[BB*SC*FF];  // quarter-LOCAL exclusive suffix of v*f
__device__ __align__(128) float g_qtU[BB*NQ*FF];  // per-quarter total of u*f
__device__ __align__(128) float g_qtV[BB*NQ*FF];  // per-quarter total of v*f

// KA: rank sort (O(N^2), warp per element) + sorted exps.
__global__ void ka_rank(const float* __restrict__ tmpl) {
    __shared__ float sh[SS];
    int tid = threadIdx.x;
    for (int i = tid; i < SS; i += 256) sh[i] = tmpl[i];
    __syncthreads();
    int e = blockIdx.x * 8 + (tid >> 5);
    int lane = tid & 31;
    float t = sh[e];
    int cnt = 0;
    #pragma unroll 8
    for (int j = lane; j < SS; j += 32) {
        float tj = sh[j];
        cnt += (tj < t) || (tj == t && j < e);
    }
    #pragma unroll
    for (int o = 16; o; o >>= 1) cnt += __shfl_down_sync(0xffffffffu, cnt, o);
    if (lane == 0) {
        g_ts[cnt] = t; g_perm[cnt] = e;
        g_us[cnt] = __expf(t); g_vs[cnt] = __expf(-t);
    }
}

// KB: P/Q scans over sorted exps (1 block, 1024 threads, Hillis-Steele)
__global__ void kb_scan() {
    __shared__ float c[1024];
    int tid = threadIdx.x;
    {
        float e0 = g_us[2*tid], e1 = g_us[2*tid+1];
        float cc = e0 + e1;
        c[tid] = cc; __syncthreads();
        for (int off = 1; off < 1024; off <<= 1) {
            float tv = c[tid];
            if (tid >= off) tv += c[tid - off];
            __syncthreads(); c[tid] = tv; __syncthreads();
        }
        float incl = c[tid];
        float excl = incl - cc;
        g_P[2*tid]   = excl;
        g_P[2*tid+1] = excl + e0;
        if (tid == 1023) g_P[SS] = incl;
        __syncthreads();
    }
    {
        float d0 = g_vs[SS-1-2*tid];
        float d1 = g_vs[SS-2-2*tid];
        float cc = d0 + d1;
        c[tid] = cc; __syncthreads();
        for (int off = 1; off < 1024; off <<= 1) {
            float tv = c[tid];
            if (tid >= off) tv += c[tid - off];
            __syncthreads(); c[tid] = tv; __syncthreads();
        }
        float incl = c[tid];
        float excl = incl - cc;
        g_Q[SS - 2*tid]     = excl;
        g_Q[SS - (2*tid+1)] = excl + d0;
        if (tid == 1023) g_Q[0] = incl;
    }
}

// K2: quarter-local sub-chunk(8) prefix/suffix tables + quarter totals.
// grid (16, 4), block 1024 = 16 slices x 64 f. Each thread owns 32 m (4 sub-chunks).
__global__ void __launch_bounds__(1024) k2_part8(const float* __restrict__ feat) {
    __shared__ float s_u[16][FF];   // 4 KB
    __shared__ float s_v[16][FF];   // 4 KB
    int tid = threadIdx.x;
    int f  = tid & 63;
    int sl = tid >> 6;               // 0..15
    int b  = blockIdx.x, q = blockIdx.y;
    const float* fb = feat + (size_t)b * SS * FF;
    int m0 = q * 512 + sl * 32;
    float r8u[4], r8v[4];
    float tu = 0.f, tv = 0.f;
    #pragma unroll
    for (int i = 0; i < 4; ++i) {
        float au = 0.f, av = 0.f;
        #pragma unroll
        for (int j = 0; j < 8; ++j) {
            int m = m0 + i*8 + j;
            float x = fb[(size_t)g_perm[m] * FF + f];
            au += g_us[m] * x;
            av += g_vs[m] * x;
        }
        r8u[i] = au; r8v[i] = av;
        tu += au; tv += av;
    }
    s_u[sl][f] = tu; s_v[sl][f] = tv;
    __syncthreads();
    float offU = 0.f, offV = 0.f, totU = 0.f, totV = 0.f;
    #pragma unroll
    for (int s2 = 0; s2 < 16; ++s2) {
        float pu = s_u[s2][f], pv = s_v[s2][f];
        if (s2 < sl) offU += pu;
        if (s2 > sl) offV += pv;
        totU += pu; totV += pv;
    }
    int cbase = b*SC + q*64 + sl*4;
    float acc = offU;
    #pragma unroll
    for (int i = 0; i < 4; ++i) {
        g_PU8[(size_t)(cbase + i)*FF + f] = acc;
        acc += r8u[i];
    }
    float accv = offV;
    #pragma unroll
    for (int i = 3; i >= 0; --i) {
        g_QV8[(size_t)(cbase + i)*FF + f] = accv;
        accv += r8v[i];
    }
    if (sl == 0) {
        g_qtU[(b*NQ + q)*FF + f] = totU;
        g_qtV[(b*NQ + q)*FF + f] = totV;
    }
}

// per-row coefficients helper
__device__ __forceinline__ void row_coeffs(float s, float& A, float& Bv, int& k) {
    int lo = 0, hi = SS;
    while (lo < hi) {
        int mid = (lo + hi) >> 1;
        if (g_ts[mid] <= s) lo = mid + 1; else hi = mid;
    }
    k = lo;
    float e  = __expf(-s);
    float ei = __expf(s);
    float inv = 1.0f / (e * g_P[k] + ei * g_Q[k]);
    A  = e * inv;
    Bv = ei * inv;
}

// KMAIN: block = 32 rows. Phase 1: coeffs (lane0/warp). Phase 2: aligned
// (warp per row, 8-elem remainder + quarter-corrected tables). Phase 3: path
// with register-cached u/v: warp owns a 256-float column segment, loops 8 rows.
__global__ void __launch_bounds__(1024) kmain(const float* __restrict__ score,
                                              const float* __restrict__ feat,
                                              const float* __restrict__ tmpl,
                                              float* __restrict__ out) {
    __shared__ float su[SS];   // 8 KB
    __shared__ float sv[SS];   // 8 KB
    __shared__ float sA[32], sB[32];
    __shared__ int   sk[32];
    int tid = threadIdx.x;
    for (int i = tid; i < SS; i += 1024) {
        float t = tmpl[i];
        su[i] = __expf(t);
        sv[i] = __expf(-t);
    }
    int w = tid >> 5, lane = tid & 31;
    int r = blockIdx.x * 32 + w;
    if (lane == 0) {
        float A, Bv; int k;
        row_coeffs(score[r], A, Bv, k);
        sA[w] = A; sB[w] = Bv; sk[w] = k;
    }
    __syncthreads();

    // ---- aligned row (warp per row) ----
    {
        float A = sA[w], Bv = sB[w];
        int k = sk[w];
        int b = r >> 11;
        int c8 = (k >= SS ? SS - 1 : k) >> 3;
        int q0 = c8 >> 6;
        int m0 = c8 * SCM;
        const float* fb = feat + (size_t)b * SS * FF;
        float aU0 = 0.f, aU1 = 0.f, aV0 = 0.f, aV1 = 0.f;
        #pragma unroll
        for (int j = 0; j < SCM; ++j) {
            int m = m0 + j;
            int p = g_perm[m];
            float um = g_us[m], vm = g_vs[m];
            const float* xr = fb + (size_t)p * FF;
            float x0 = xr[lane], x1 = xr[lane + 32];
            if (m < k) { aU0 += um * x0; aU1 += um * x1; }
            else       { aV0 += vm * x0; aV1 += vm * x1; }
        }
        // cross-quarter totals
        #pragma unroll
        for (int q = 0; q < NQ; ++q) {
            int qb = (b*NQ + q)*FF;
            if (q < q0) {
                aU0 += g_qtU[qb + lane];
                aU1 += g_qtU[qb + lane + 32];
            }
            if (q > q0) {
                aV0 += g_qtV[qb + lane];
                aV1 += g_qtV[qb + lane + 32];
            }
        }
        size_t base = (size_t)(b*SC + c8)*FF;
        out[(size_t)r * FF + lane]      = A*(g_PU8[base + lane]      + aU0) + Bv*(g_QV8[base + lane]      + aV0);
        out[(size_t)r * FF + lane + 32] = A*(g_PU8[base + lane + 32] + aU1) + Bv*(g_QV8[base + lane + 32] + aV1);
    }

    // ---- path (warp owns column segment, loops 8 rows) ----
    {
        const float4* su4 = reinterpret_cast<const float4*>(su);
        const float4* sv4 = reinterpret_cast<const float4*>(sv);
        int seg = w & 7;          // column segment 0..7 (64 float4 each)
        int rg  = w >> 3;         // row group 0..3 (8 rows each)
        int j4 = seg * 64 + lane;
        float4 u0 = su4[j4],      v0 = sv4[j4];
        float4 u1 = su4[j4 + 32], v1 = sv4[j4 + 32];
        float* pbase = out + (size_t)RR * FF;
        #pragma unroll
        for (int rr = 0; rr < 8; ++rr) {
            int lr = rg * 8 + rr;
            float A = sA[lr], Bv = sB[lr];
            int r2 = blockIdx.x * 32 + lr;
            float4 p0, p1;
            p0.x = fminf(A*u0.x, Bv*v0.x);
            p0.y = fminf(A*u0.y, Bv*v0.y);
            p0.z = fminf(A*u0.z, Bv*v0.z);
            p0.w = fminf(A*u0.w, Bv*v0.w);
            p1.x = fminf(A*u1.x, Bv*v1.x);
            p1.y = fminf(A*u1.y, Bv*v1.y);
            p1.z = fminf(A*u1.z, Bv*v1.z);
            p1.w = fminf(A*u1.w, Bv*v1.w);
            float4* prow = reinterpret_cast<float4*>(pbase + (size_t)r2 * SS);
            __stcs(prow + j4, p0);
            __stcs(prow + j4 + 32, p1);
        }
    }
}

extern "C" void kernel_launch(void* const* d_in, const int* in_sizes, int n_in,
                              void* d_out, int out_size) {
    const float* score = (const float*)d_in[0];   // [16,2048,1]
    const float* feat  = (const float*)d_in[1];   // [16,2048,64]
    const float* tmpl  = (const float*)d_in[2];   // [1,2048,1]
    float* out = (float*)d_out;                   // aligned [16,2048,64] then path [16,2048,2048]

    ka_rank<<<SS/8, 256>>>(tmpl);
    kb_scan<<<1, 1024>>>();
    k2_part8<<<dim3(BB, NQ), 1024>>>(feat);
    kmain<<<RR/32, 1024>>>(score, feat, tmpl, out);
}